// round 7
// baseline (speedup 1.0000x reference)
#include <cuda_runtime.h>
#include <cuda_bf16.h>
#include <math_constants.h>

// Problem constants
#define B 2
#define L 1024
#define E 1024
#define H 16
#define NT (B*L)          // 2048 tokens
#define LOG2E 1.4426950408889634f
#define KSPLIT 4

typedef unsigned long long u64;

// -------- scratch (static __device__, no allocations) --------
__device__ float4 g_xn4[NT * (E/4)];             // layernormed x, 8MB
__device__ float  g_projp[KSPLIT][NT * 240];     // QKV projection partials
__device__ float4 g_Q[B*H*L * 2];                // per (b,h,i): (alpha'*Qr, q2), (qd, -beta')
__device__ float4 g_K[B*H*L * 3];                // per (b,h,j): (Kr, k2), (-2kd, maskpen'), (V, 0)
__device__ float  g_O[NT * H * 3];               // attention output (B,L,H,3)

// ---------------- f32x2 helpers ----------------
__device__ __forceinline__ u64 pk2(float lo, float hi)
{ u64 r; asm("mov.b64 %0, {%1,%2};" : "=l"(r) : "f"(lo), "f"(hi)); return r; }
__device__ __forceinline__ u64 bc2(float v) { return pk2(v, v); }
__device__ __forceinline__ void up2(float &lo, float &hi, u64 v)
{ asm("mov.b64 {%0,%1}, %2;" : "=f"(lo), "=f"(hi) : "l"(v)); }
__device__ __forceinline__ u64 fma2(u64 a, u64 b, u64 c)
{ u64 d; asm("fma.rn.f32x2 %0, %1, %2, %3;" : "=l"(d) : "l"(a), "l"(b), "l"(c)); return d; }
__device__ __forceinline__ u64 add2(u64 a, u64 b)
{ u64 d; asm("add.rn.f32x2 %0, %1, %2;" : "=l"(d) : "l"(a), "l"(b)); return d; }

// ============================================================
// K1: LayerNorm  (one block per token, 256 threads, float4)
// ============================================================
__global__ void __launch_bounds__(256) ln_kernel(const float* __restrict__ x,
                                                 const float* __restrict__ gamma,
                                                 const float* __restrict__ beta)
{
    int t   = blockIdx.x;
    int tid = threadIdx.x;
    const float4* xr = (const float4*)(x + (size_t)t * E);
    float4 v = xr[tid];
    float s  = v.x + v.y + v.z + v.w;
    float ss = v.x*v.x + v.y*v.y + v.z*v.z + v.w*v.w;
    #pragma unroll
    for (int o = 16; o; o >>= 1) {
        s  += __shfl_xor_sync(0xFFFFFFFFu, s,  o);
        ss += __shfl_xor_sync(0xFFFFFFFFu, ss, o);
    }
    __shared__ float sm[8], sm2[8];
    __shared__ float mu_s, rstd_s;
    if ((tid & 31) == 0) { sm[tid >> 5] = s; sm2[tid >> 5] = ss; }
    __syncthreads();
    if (tid == 0) {
        float S = 0.f, SS = 0.f;
        #pragma unroll
        for (int i = 0; i < 8; i++) { S += sm[i]; SS += sm2[i]; }
        float mu  = S * (1.0f / E);
        float var = SS * (1.0f / E) - mu * mu;
        mu_s   = mu;
        rstd_s = rsqrtf(var + 1e-5f);
    }
    __syncthreads();
    float mu = mu_s, r = rstd_s;
    float4 g  = ((const float4*)gamma)[tid];
    float4 be = ((const float4*)beta)[tid];
    float4 o;
    o.x = (v.x - mu) * r * g.x + be.x;
    o.y = (v.y - mu) * r * g.y + be.y;
    o.z = (v.z - mu) * r * g.z + be.z;
    o.w = (v.w - mu) * r * g.w + be.w;
    g_xn4[t * (E/4) + tid] = o;
}

// ============================================================
// K2: QKV GEMM, f32x2, smem-BW-optimized tiling.
// C[2048x240] = xn[2048x1024] @ Wqkv[1024x240]
// BM=128 BN=48, K-split 4 (z), 64 threads, micro 16 rows x 6 cols.
// Per kk: 4 LDS.128 (A) + 3 LDS.128 (B dup) = 112B per 96 MAC.
// ============================================================
#define AS_STRIDE 132   // padded (16B-aligned, de-conflicted)
#define BS_STRIDE 100   // padded (16B-aligned, de-conflicted)

__global__ void __launch_bounds__(64) qkv_gemm(const float* __restrict__ W)
{
    __shared__ float As[16 * AS_STRIDE];   // [kk][row], 8.4KB
    __shared__ float Bs[16 * BS_STRIDE];   // [kk][2*col] duplicated, 6.4KB

    const float* xn = (const float*)g_xn4;
    int bm = blockIdx.x * 128;
    int bn = blockIdx.y * 48;
    int kh = blockIdx.z;                 // K quarter: 0..3
    int t  = threadIdx.x;
    int ty = t >> 3;                     // 0..7  -> rows ty*16
    int tx = t & 7;                      // 0..7  -> cols tx*6

    u64 acc[8][6];
    #pragma unroll
    for (int i = 0; i < 8; i++)
        #pragma unroll
        for (int c = 0; c < 6; c++) acc[i][c] = 0ull;

    // B staging map: 16kk x 48 cols, 12 source floats per thread
    int bk = t >> 2;                     // 0..15
    int bc = (t & 3) * 12;               // 0,12,24,36

    const int KQ = 1024 / KSPLIT;        // 256
    for (int k0 = kh * KQ; k0 < kh * KQ + KQ; k0 += 16) {
        // stage A: 128 rows x 16 k  (512 float4, 8 per thread)
        #pragma unroll
        for (int i = 0; i < 8; i++) {
            int idx4 = t + 64 * i;           // 0..511
            int row  = idx4 >> 2;
            int kc   = (idx4 & 3) * 4;
            float4 av = *(const float4*)(xn + (size_t)(bm + row) * E + k0 + kc);
            As[(kc + 0) * AS_STRIDE + row] = av.x;
            As[(kc + 1) * AS_STRIDE + row] = av.y;
            As[(kc + 2) * AS_STRIDE + row] = av.z;
            As[(kc + 3) * AS_STRIDE + row] = av.w;
        }
        // stage B duplicated: 16 k x 48 cols (12 floats per thread, 3 float4)
        {
            const float* wp = W + (size_t)(k0 + bk) * 240 + bn + bc;
            float* bs = &Bs[bk * BS_STRIDE + bc * 2];
            #pragma unroll
            for (int q = 0; q < 3; q++) {
                float4 bv = *(const float4*)(wp + q * 4);
                bs[q*8 + 0] = bv.x; bs[q*8 + 1] = bv.x;
                bs[q*8 + 2] = bv.y; bs[q*8 + 3] = bv.y;
                bs[q*8 + 4] = bv.z; bs[q*8 + 5] = bv.z;
                bs[q*8 + 6] = bv.w; bs[q*8 + 7] = bv.w;
            }
        }
        __syncthreads();
        #pragma unroll
        for (int kk = 0; kk < 16; kk++) {
            const float* arow = &As[kk * AS_STRIDE + ty * 16];
            const float* brow = &Bs[kk * BS_STRIDE + tx * 12];
            ulonglong2 a01 = *(const ulonglong2*)(arow + 0);
            ulonglong2 a23 = *(const ulonglong2*)(arow + 4);
            ulonglong2 a45 = *(const ulonglong2*)(arow + 8);
            ulonglong2 a67 = *(const ulonglong2*)(arow + 12);
            ulonglong2 b01 = *(const ulonglong2*)(brow + 0);
            ulonglong2 b23 = *(const ulonglong2*)(brow + 4);
            ulonglong2 b45 = *(const ulonglong2*)(brow + 8);
            u64 a[8] = {a01.x, a01.y, a23.x, a23.y, a45.x, a45.y, a67.x, a67.y};
            u64 bb[6] = {b01.x, b01.y, b23.x, b23.y, b45.x, b45.y};
            #pragma unroll
            for (int i = 0; i < 8; i++) {
                acc[i][0] = fma2(a[i], bb[0], acc[i][0]);
                acc[i][1] = fma2(a[i], bb[1], acc[i][1]);
                acc[i][2] = fma2(a[i], bb[2], acc[i][2]);
                acc[i][3] = fma2(a[i], bb[3], acc[i][3]);
                acc[i][4] = fma2(a[i], bb[4], acc[i][4]);
                acc[i][5] = fma2(a[i], bb[5], acc[i][5]);
            }
        }
        __syncthreads();
    }

    float* out = g_projp[kh];
    #pragma unroll
    for (int i = 0; i < 8; i++) {
        int row = bm + ty * 16 + 2 * i;
        #pragma unroll
        for (int c = 0; c < 6; c++) {
            float lo, hi;
            up2(lo, hi, acc[i][c]);
            int col = bn + tx * 6 + c;
            out[(size_t)row * 240 + col]       = lo;
            out[(size_t)(row + 1) * 240 + col] = hi;
        }
    }
}

// ============================================================
// K2b: rotate + translate + pack per (token, head)
// ============================================================
__device__ __forceinline__ float softplus_f(float x)
{
    return (x > 20.f) ? x : log1pf(__expf(x));
}

__global__ void __launch_bounds__(256) pack_kernel(const float* __restrict__ rot,
                                                   const float* __restrict__ trans,
                                                   const unsigned char* __restrict__ mask,
                                                   const float* __restrict__ r_scale,
                                                   const float* __restrict__ d_scale)
{
    int gid = blockIdx.x * blockDim.x + threadIdx.x;
    if (gid >= NT * H) return;
    int t = gid >> 4;
    int h = gid & 15;

    float R[9];
    #pragma unroll
    for (int i = 0; i < 9; i++) R[i] = rot[t*9 + i];
    float T0 = trans[t*3+0], T1 = trans[t*3+1], T2 = trans[t*3+2];

    float y[5][3];
    #pragma unroll
    for (int f = 0; f < 5; f++) {
        int o = f*48 + h*3;
        float v0 = 0.f, v1 = 0.f, v2 = 0.f;
        #pragma unroll
        for (int q = 0; q < KSPLIT; q++) {
            const float* P = g_projp[q] + (size_t)t * 240;
            v0 += P[o+0]; v1 += P[o+1]; v2 += P[o+2];
        }
        y[f][0] = R[0]*v0 + R[1]*v1 + R[2]*v2;
        y[f][1] = R[3]*v0 + R[4]*v1 + R[5]*v2;
        y[f][2] = R[6]*v0 + R[7]*v1 + R[8]*v2;
    }
    const float scale = 0.5773502691896258f;      // 3^-0.5
    float alpha = softplus_f(r_scale[h]) * scale * LOG2E;
    float nbeta = -softplus_f(d_scale[h]) * scale * LOG2E;

    float qd0 = y[2][0] + T0, qd1 = y[2][1] + T1, qd2 = y[2][2] + T2;
    float q2  = qd0*qd0 + qd1*qd1 + qd2*qd2;
    float kd0 = y[3][0] + T0, kd1 = y[3][1] + T1, kd2 = y[3][2] + T2;
    float k2  = kd0*kd0 + kd1*kd1 + kd2*kd2;

    int b = t >> 10, l = t & 1023;
    int base = (b*H + h) * L + l;

    g_Q[base*2 + 0] = make_float4(alpha*y[0][0], alpha*y[0][1], alpha*y[0][2], q2);
    g_Q[base*2 + 1] = make_float4(qd0, qd1, qd2, nbeta);

    float mpen = mask[t] ? -2.0e9f : 0.f;   // in log2 units; EX2 -> 0
    g_K[base*3 + 0] = make_float4(y[1][0], y[1][1], y[1][2], k2);
    g_K[base*3 + 1] = make_float4(-2.f*kd0, -2.f*kd1, -2.f*kd2, mpen);
    g_K[base*3 + 2] = make_float4(y[4][0], y[4][1], y[4][2], 0.f);
}

// ============================================================
// K3: flash attention, geometric logits, no online max, f32x2 packed
// over row-pairs. Block: 8 warps x 4 rows = 32 i-rows; lanes split j.
// grid (B*H, L/32).  3 blocks/SM.   (proven version)
// ============================================================
__global__ void __launch_bounds__(256, 3) attn_kernel()
{
    __shared__ float4 sk[L * 3];   // 49152 bytes

    int bh    = blockIdx.x;        // b*H + h
    int itile = blockIdx.y;        // 0..31

    const float4* Ksrc = g_K + (size_t)bh * L * 3;
    #pragma unroll
    for (int i = 0; i < 12; i++) sk[threadIdx.x + 256 * i] = Ksrc[threadIdx.x + 256 * i];
    __syncthreads();

    int warp = threadIdx.x >> 5, lane = threadIdx.x & 31;
    int rbase = itile * 32 + warp * 4;

    const float4* Qsrc = g_Q + (size_t)(bh * L + rbase) * 2;
    u64 QRX[2], QRY[2], QRZ[2], Q2[2], QDX[2], QDY[2], QDZ[2];
    u64 S[2], A0[2], A1[2], A2[2];
    u64 NB;
    #pragma unroll
    for (int p = 0; p < 2; p++) {
        float4 alo = Qsrc[(2*p)*2],     blo = Qsrc[(2*p)*2 + 1];
        float4 ahi = Qsrc[(2*p+1)*2],   bhi = Qsrc[(2*p+1)*2 + 1];
        QRX[p] = pk2(alo.x, ahi.x); QRY[p] = pk2(alo.y, ahi.y);
        QRZ[p] = pk2(alo.z, ahi.z); Q2 [p] = pk2(alo.w, ahi.w);
        QDX[p] = pk2(blo.x, bhi.x); QDY[p] = pk2(blo.y, bhi.y);
        QDZ[p] = pk2(blo.z, bhi.z);
        if (p == 0) NB = bc2(blo.w);
        S[p] = 0ull; A0[p] = 0ull; A1[p] = 0ull; A2[p] = 0ull;
    }

    #pragma unroll 4
    for (int jj = 0; jj < 32; jj++) {
        int j = jj * 32 + lane;
        float4 kr = sk[j*3 + 0];
        float4 kd = sk[j*3 + 1];
        float4 vv = sk[j*3 + 2];
        u64 KRX = bc2(kr.x), KRY = bc2(kr.y), KRZ = bc2(kr.z), KRW = bc2(kr.w);
        u64 KDX = bc2(kd.x), KDY = bc2(kd.y), KDZ = bc2(kd.z), KDW = bc2(kd.w);
        u64 VX  = bc2(vv.x), VY  = bc2(vv.y), VZ  = bc2(vv.z);
        #pragma unroll
        for (int p = 0; p < 2; p++) {
            u64 t1 = fma2(QRX[p], KRX, KDW);
            t1 = fma2(QRY[p], KRY, t1);
            t1 = fma2(QRZ[p], KRZ, t1);
            u64 d2 = add2(Q2[p], KRW);
            d2 = fma2(QDX[p], KDX, d2);
            d2 = fma2(QDY[p], KDY, d2);
            d2 = fma2(QDZ[p], KDZ, d2);
            float d2a, d2b;
            up2(d2a, d2b, d2);
            float da, db, pa, pb;
            float ada = fabsf(d2a), adb = fabsf(d2b);
            asm("sqrt.approx.f32 %0, %1;" : "=f"(da) : "f"(ada));
            asm("sqrt.approx.f32 %0, %1;" : "=f"(db) : "f"(adb));
            u64 DD = pk2(da, db);
            u64 ARG = fma2(NB, DD, t1);
            float arga, argb;
            up2(arga, argb, ARG);
            asm("ex2.approx.f32 %0, %1;" : "=f"(pa) : "f"(arga));
            asm("ex2.approx.f32 %0, %1;" : "=f"(pb) : "f"(argb));
            u64 P = pk2(pa, pb);
            S [p] = add2(S[p], P);
            A0[p] = fma2(P, VX, A0[p]);
            A1[p] = fma2(P, VY, A1[p]);
            A2[p] = fma2(P, VZ, A2[p]);
        }
    }

    // cross-lane sum reduce
    int b = bh >> 4, h = bh & 15;
    #pragma unroll
    for (int p = 0; p < 2; p++) {
        float s0, s1, x0, x1, y0, y1, z0, z1;
        up2(s0, s1, S[p]); up2(x0, x1, A0[p]); up2(y0, y1, A1[p]); up2(z0, z1, A2[p]);
        #pragma unroll
        for (int o = 16; o; o >>= 1) {
            s0 += __shfl_xor_sync(0xFFFFFFFFu, s0, o);
            x0 += __shfl_xor_sync(0xFFFFFFFFu, x0, o);
            y0 += __shfl_xor_sync(0xFFFFFFFFu, y0, o);
            z0 += __shfl_xor_sync(0xFFFFFFFFu, z0, o);
            s1 += __shfl_xor_sync(0xFFFFFFFFu, s1, o);
            x1 += __shfl_xor_sync(0xFFFFFFFFu, x1, o);
            y1 += __shfl_xor_sync(0xFFFFFFFFu, y1, o);
            z1 += __shfl_xor_sync(0xFFFFFFFFu, z1, o);
        }
        if (lane == 0) {
            float inv0, inv1;
            asm("rcp.approx.f32 %0, %1;" : "=f"(inv0) : "f"(s0));
            asm("rcp.approx.f32 %0, %1;" : "=f"(inv1) : "f"(s1));
            int row0 = rbase + 2*p;
            float* op0 = g_O + ((size_t)(b * L + row0) * H + h) * 3;
            float* op1 = g_O + ((size_t)(b * L + row0 + 1) * H + h) * 3;
            op0[0] = x0 * inv0; op0[1] = y0 * inv0; op0[2] = z0 * inv0;
            op1[0] = x1 * inv1; op1[1] = y1 * inv1; op1[2] = z1 * inv1;
        }
    }
}

// ============================================================
// K4: rotate back (R^T) + output GEMM (48 -> 1024) + bias, f32x2
// ============================================================
__global__ void __launch_bounds__(256) out_kernel(const float* __restrict__ rot,
                                                  const float* __restrict__ Wout,
                                                  const float* __restrict__ bout,
                                                  float* __restrict__ out)
{
    __shared__ float so[48][8];    // [k][token]
    int t0  = blockIdx.x * 8;
    int tid = threadIdx.x;

    if (tid < 128) {
        int tt = tid >> 4, h = tid & 15;
        int t = t0 + tt;
        const float* op = g_O + ((size_t)t * H + h) * 3;
        float R0 = rot[t*9+0], R1 = rot[t*9+1], R2 = rot[t*9+2];
        float R3 = rot[t*9+3], R4 = rot[t*9+4], R5 = rot[t*9+5];
        float R6 = rot[t*9+6], R7 = rot[t*9+7], R8 = rot[t*9+8];
        float o0 = op[0], o1 = op[1], o2 = op[2];
        so[h*3+0][tt] = R0*o0 + R3*o1 + R6*o2;
        so[h*3+1][tt] = R1*o0 + R4*o1 + R7*o2;
        so[h*3+2][tt] = R2*o0 + R5*o1 + R8*o2;
    }
    __syncthreads();

    int e0 = tid;   // cols e0, e0+256, e0+512, e0+768
    u64 acc[4][4];  // [tokenpair][colgroup]
    #pragma unroll
    for (int c = 0; c < 4; c++) {
        float bb = bout[e0 + 256*c];
        u64 bb2 = bc2(bb);
        #pragma unroll
        for (int tp = 0; tp < 4; tp++) acc[tp][c] = bb2;
    }

    #pragma unroll 4
    for (int k = 0; k < 48; k++) {
        u64 w2[4];
        #pragma unroll
        for (int c = 0; c < 4; c++) w2[c] = bc2(Wout[(size_t)k*E + e0 + 256*c]);
        const u64* sop = (const u64*)&so[k][0];
        #pragma unroll
        for (int tp = 0; tp < 4; tp++) {
            u64 sv = sop[tp];
            acc[tp][0] = fma2(sv, w2[0], acc[tp][0]);
            acc[tp][1] = fma2(sv, w2[1], acc[tp][1]);
            acc[tp][2] = fma2(sv, w2[2], acc[tp][2]);
            acc[tp][3] = fma2(sv, w2[3], acc[tp][3]);
        }
    }
    #pragma unroll
    for (int tp = 0; tp < 4; tp++) {
        float* orow0 = out + (size_t)(t0 + 2*tp) * E;
        float* orow1 = out + (size_t)(t0 + 2*tp + 1) * E;
        #pragma unroll
        for (int c = 0; c < 4; c++) {
            float lo, hi;
            up2(lo, hi, acc[tp][c]);
            orow0[e0 + 256*c] = lo;
            orow1[e0 + 256*c] = hi;
        }
    }
}

// ============================================================
extern "C" void kernel_launch(void* const* d_in, const int* in_sizes, int n_in,
                              void* d_out, int out_size)
{
    const float*         x       = (const float*)d_in[0];
    const float*         rot     = (const float*)d_in[1];
    const float*         trans   = (const float*)d_in[2];
    const unsigned char* mask    = (const unsigned char*)d_in[3];
    const float*         Wqkv    = (const float*)d_in[4];
    const float*         Wout    = (const float*)d_in[5];
    const float*         bout    = (const float*)d_in[6];
    const float*         gamma   = (const float*)d_in[7];
    const float*         beta    = (const float*)d_in[8];
    const float*         r_scale = (const float*)d_in[9];
    const float*         d_scale = (const float*)d_in[10];
    float* out = (float*)d_out;

    ln_kernel<<<NT, 256>>>(x, gamma, beta);
    qkv_gemm<<<dim3(NT/128, 5, KSPLIT), 64>>>(Wqkv);
    pack_kernel<<<(NT*H + 255)/256, 256>>>(rot, trans, mask, r_scale, d_scale);
    attn_kernel<<<dim3(B*H, L/32), 256>>>();
    out_kernel<<<NT/8, 256>>>(rot, Wout, bout, out);
}

// round 8
// speedup vs baseline: 1.0698x; 1.0698x over previous
#include <cuda_runtime.h>
#include <cuda_bf16.h>
#include <math_constants.h>

// Problem constants
#define B 2
#define L 1024
#define E 1024
#define H 16
#define NT (B*L)          // 2048 tokens
#define LOG2E 1.4426950408889634f
#define KSPLIT 8

typedef unsigned long long u64;

// -------- scratch (static __device__, no allocations) --------
__device__ float4 g_xn4[NT * (E/4)];             // layernormed x, 8MB
__device__ float  g_projp[KSPLIT][NT * 240];     // QKV projection partials
__device__ float4 g_Q[B*H*L * 2];                // per (b,h,i): (alpha'*Qr, q2), (qd, -beta')
__device__ float4 g_K[B*H*L * 3];                // per (b,h,j): (Kr, k2), (-2kd, maskpen'), (V, 0)
__device__ float  g_O[NT * H * 3];               // attention output (B,L,H,3)

// ---------------- f32x2 helpers ----------------
__device__ __forceinline__ u64 pk2(float lo, float hi)
{ u64 r; asm("mov.b64 %0, {%1,%2};" : "=l"(r) : "f"(lo), "f"(hi)); return r; }
__device__ __forceinline__ u64 bc2(float v) { return pk2(v, v); }
__device__ __forceinline__ void up2(float &lo, float &hi, u64 v)
{ asm("mov.b64 {%0,%1}, %2;" : "=f"(lo), "=f"(hi) : "l"(v)); }
__device__ __forceinline__ u64 fma2(u64 a, u64 b, u64 c)
{ u64 d; asm("fma.rn.f32x2 %0, %1, %2, %3;" : "=l"(d) : "l"(a), "l"(b), "l"(c)); return d; }
__device__ __forceinline__ u64 add2(u64 a, u64 b)
{ u64 d; asm("add.rn.f32x2 %0, %1, %2;" : "=l"(d) : "l"(a), "l"(b)); return d; }

// ============================================================
// K1: LayerNorm  (one block per token, 256 threads, float4)
// ============================================================
__global__ void __launch_bounds__(256) ln_kernel(const float* __restrict__ x,
                                                 const float* __restrict__ gamma,
                                                 const float* __restrict__ beta)
{
    int t   = blockIdx.x;
    int tid = threadIdx.x;
    const float4* xr = (const float4*)(x + (size_t)t * E);
    float4 v = xr[tid];
    float s  = v.x + v.y + v.z + v.w;
    float ss = v.x*v.x + v.y*v.y + v.z*v.z + v.w*v.w;
    #pragma unroll
    for (int o = 16; o; o >>= 1) {
        s  += __shfl_xor_sync(0xFFFFFFFFu, s,  o);
        ss += __shfl_xor_sync(0xFFFFFFFFu, ss, o);
    }
    __shared__ float sm[8], sm2[8];
    __shared__ float mu_s, rstd_s;
    if ((tid & 31) == 0) { sm[tid >> 5] = s; sm2[tid >> 5] = ss; }
    __syncthreads();
    if (tid == 0) {
        float S = 0.f, SS = 0.f;
        #pragma unroll
        for (int i = 0; i < 8; i++) { S += sm[i]; SS += sm2[i]; }
        float mu  = S * (1.0f / E);
        float var = SS * (1.0f / E) - mu * mu;
        mu_s   = mu;
        rstd_s = rsqrtf(var + 1e-5f);
    }
    __syncthreads();
    float mu = mu_s, r = rstd_s;
    float4 g  = ((const float4*)gamma)[tid];
    float4 be = ((const float4*)beta)[tid];
    float4 o;
    o.x = (v.x - mu) * r * g.x + be.x;
    o.y = (v.y - mu) * r * g.y + be.y;
    o.z = (v.z - mu) * r * g.z + be.z;
    o.w = (v.w - mu) * r * g.w + be.w;
    g_xn4[t * (E/4) + tid] = o;
}

// ============================================================
// K2: QKV GEMM with packed f32x2 FFMA.  (round-3 proven tiling)
// C[2048x240] = xn[2048x1024] @ Wqkv[1024x240]
// BM=64 BN=48, K-split 8 (z), 128 threads, micro 8 rows x 3 cols.
// ============================================================
__global__ void __launch_bounds__(128) qkv_gemm(const float* __restrict__ W)
{
    __shared__ float As[16][64];   // [k][row]
    __shared__ float Bs[16][96];   // [k][2*col] duplicated

    const float* xn = (const float*)g_xn4;
    int bm = blockIdx.x * 64;
    int bn = blockIdx.y * 48;
    int kh = blockIdx.z;                 // K eighth: 0..7
    int t  = threadIdx.x;
    int ty = t >> 4;                     // 0..7  -> rows ty*8
    int tx = t & 15;                     // 0..15 -> cols tx*3

    u64 acc[4][3];
    #pragma unroll
    for (int i = 0; i < 4; i++)
        #pragma unroll
        for (int c = 0; c < 3; c++) acc[i][c] = 0ull;

    int bk = t >> 3;                     // 0..15
    int bc = (t & 7) * 6;                // 0,6,...,42

    const int KQ = 1024 / KSPLIT;        // 128
    for (int k0 = kh * KQ; k0 < kh * KQ + KQ; k0 += 16) {
        #pragma unroll
        for (int i = 0; i < 2; i++) {
            int idx4 = t + 128 * i;          // 0..255
            int row  = idx4 >> 2;
            int kc   = (idx4 & 3) * 4;
            float4 av = *(const float4*)(xn + (size_t)(bm + row) * E + k0 + kc);
            As[kc + 0][row] = av.x;
            As[kc + 1][row] = av.y;
            As[kc + 2][row] = av.z;
            As[kc + 3][row] = av.w;
        }
        {
            const float* wp = W + (size_t)(k0 + bk) * 240 + bn + bc;
            float2 b0 = *(const float2*)(wp + 0);
            float2 b1 = *(const float2*)(wp + 2);
            float2 b2 = *(const float2*)(wp + 4);
            float* bs = &Bs[bk][bc * 2];
            bs[0] = b0.x; bs[1] = b0.x; bs[2]  = b0.y; bs[3]  = b0.y;
            bs[4] = b1.x; bs[5] = b1.x; bs[6]  = b1.y; bs[7]  = b1.y;
            bs[8] = b2.x; bs[9] = b2.x; bs[10] = b2.y; bs[11] = b2.y;
        }
        __syncthreads();
        #pragma unroll
        for (int kk = 0; kk < 16; kk++) {
            ulonglong2 a01 = *(const ulonglong2*)&As[kk][ty * 8];
            ulonglong2 a23 = *(const ulonglong2*)&As[kk][ty * 8 + 4];
            u64 b0 = *(const u64*)&Bs[kk][tx * 6 + 0];
            u64 b1 = *(const u64*)&Bs[kk][tx * 6 + 2];
            u64 b2 = *(const u64*)&Bs[kk][tx * 6 + 4];
            acc[0][0]=fma2(a01.x,b0,acc[0][0]); acc[0][1]=fma2(a01.x,b1,acc[0][1]); acc[0][2]=fma2(a01.x,b2,acc[0][2]);
            acc[1][0]=fma2(a01.y,b0,acc[1][0]); acc[1][1]=fma2(a01.y,b1,acc[1][1]); acc[1][2]=fma2(a01.y,b2,acc[1][2]);
            acc[2][0]=fma2(a23.x,b0,acc[2][0]); acc[2][1]=fma2(a23.x,b1,acc[2][1]); acc[2][2]=fma2(a23.x,b2,acc[2][2]);
            acc[3][0]=fma2(a23.y,b0,acc[3][0]); acc[3][1]=fma2(a23.y,b1,acc[3][1]); acc[3][2]=fma2(a23.y,b2,acc[3][2]);
        }
        __syncthreads();
    }

    float* out = g_projp[kh];
    #pragma unroll
    for (int i = 0; i < 4; i++) {
        int row = bm + ty * 8 + 2 * i;
        #pragma unroll
        for (int c = 0; c < 3; c++) {
            float lo, hi;
            up2(lo, hi, acc[i][c]);
            int col = bn + tx * 3 + c;
            out[(size_t)row * 240 + col]       = lo;
            out[(size_t)(row + 1) * 240 + col] = hi;
        }
    }
}

// ============================================================
// K2b: rotate + translate + pack per (token, head)
// ============================================================
__device__ __forceinline__ float softplus_f(float x)
{
    return (x > 20.f) ? x : log1pf(__expf(x));
}

__global__ void __launch_bounds__(256) pack_kernel(const float* __restrict__ rot,
                                                   const float* __restrict__ trans,
                                                   const unsigned char* __restrict__ mask,
                                                   const float* __restrict__ r_scale,
                                                   const float* __restrict__ d_scale)
{
    int gid = blockIdx.x * blockDim.x + threadIdx.x;
    if (gid >= NT * H) return;
    int t = gid >> 4;
    int h = gid & 15;

    float R[9];
    #pragma unroll
    for (int i = 0; i < 9; i++) R[i] = rot[t*9 + i];
    float T0 = trans[t*3+0], T1 = trans[t*3+1], T2 = trans[t*3+2];

    float y[5][3];
    #pragma unroll
    for (int f = 0; f < 5; f++) {
        int o = f*48 + h*3;
        float v0 = 0.f, v1 = 0.f, v2 = 0.f;
        #pragma unroll
        for (int q = 0; q < KSPLIT; q++) {
            const float* P = g_projp[q] + (size_t)t * 240;
            v0 += P[o+0]; v1 += P[o+1]; v2 += P[o+2];
        }
        y[f][0] = R[0]*v0 + R[1]*v1 + R[2]*v2;
        y[f][1] = R[3]*v0 + R[4]*v1 + R[5]*v2;
        y[f][2] = R[6]*v0 + R[7]*v1 + R[8]*v2;
    }
    const float scale = 0.5773502691896258f;      // 3^-0.5
    float alpha = softplus_f(r_scale[h]) * scale * LOG2E;
    float nbeta = -softplus_f(d_scale[h]) * scale * LOG2E;

    float qd0 = y[2][0] + T0, qd1 = y[2][1] + T1, qd2 = y[2][2] + T2;
    float q2  = qd0*qd0 + qd1*qd1 + qd2*qd2;
    float kd0 = y[3][0] + T0, kd1 = y[3][1] + T1, kd2 = y[3][2] + T2;
    float k2  = kd0*kd0 + kd1*kd1 + kd2*kd2;

    int b = t >> 10, l = t & 1023;
    int base = (b*H + h) * L + l;

    g_Q[base*2 + 0] = make_float4(alpha*y[0][0], alpha*y[0][1], alpha*y[0][2], q2);
    g_Q[base*2 + 1] = make_float4(qd0, qd1, qd2, nbeta);

    float mpen = mask[t] ? -2.0e9f : 0.f;   // in log2 units; EX2 -> 0
    g_K[base*3 + 0] = make_float4(y[1][0], y[1][1], y[1][2], k2);
    g_K[base*3 + 1] = make_float4(-2.f*kd0, -2.f*kd1, -2.f*kd2, mpen);
    g_K[base*3 + 2] = make_float4(y[4][0], y[4][1], y[4][2], 0.f);
}

// ============================================================
// K3: flash attention, geometric logits, no online max, f32x2 packed
// over row-pairs. Block: 8 warps x 4 rows = 32 i-rows; lanes split j.
// grid (B*H, L/32).  3 blocks/SM.   (proven version, unchanged)
// ============================================================
__global__ void __launch_bounds__(256, 3) attn_kernel()
{
    __shared__ float4 sk[L * 3];   // 49152 bytes

    int bh    = blockIdx.x;        // b*H + h
    int itile = blockIdx.y;        // 0..31

    const float4* Ksrc = g_K + (size_t)bh * L * 3;
    #pragma unroll
    for (int i = 0; i < 12; i++) sk[threadIdx.x + 256 * i] = Ksrc[threadIdx.x + 256 * i];
    __syncthreads();

    int warp = threadIdx.x >> 5, lane = threadIdx.x & 31;
    int rbase = itile * 32 + warp * 4;

    const float4* Qsrc = g_Q + (size_t)(bh * L + rbase) * 2;
    u64 QRX[2], QRY[2], QRZ[2], Q2[2], QDX[2], QDY[2], QDZ[2];
    u64 S[2], A0[2], A1[2], A2[2];
    u64 NB;
    #pragma unroll
    for (int p = 0; p < 2; p++) {
        float4 alo = Qsrc[(2*p)*2],     blo = Qsrc[(2*p)*2 + 1];
        float4 ahi = Qsrc[(2*p+1)*2],   bhi = Qsrc[(2*p+1)*2 + 1];
        QRX[p] = pk2(alo.x, ahi.x); QRY[p] = pk2(alo.y, ahi.y);
        QRZ[p] = pk2(alo.z, ahi.z); Q2 [p] = pk2(alo.w, ahi.w);
        QDX[p] = pk2(blo.x, bhi.x); QDY[p] = pk2(blo.y, bhi.y);
        QDZ[p] = pk2(blo.z, bhi.z);
        if (p == 0) NB = bc2(blo.w);
        S[p] = 0ull; A0[p] = 0ull; A1[p] = 0ull; A2[p] = 0ull;
    }

    #pragma unroll 4
    for (int jj = 0; jj < 32; jj++) {
        int j = jj * 32 + lane;
        float4 kr = sk[j*3 + 0];
        float4 kd = sk[j*3 + 1];
        float4 vv = sk[j*3 + 2];
        u64 KRX = bc2(kr.x), KRY = bc2(kr.y), KRZ = bc2(kr.z), KRW = bc2(kr.w);
        u64 KDX = bc2(kd.x), KDY = bc2(kd.y), KDZ = bc2(kd.z), KDW = bc2(kd.w);
        u64 VX  = bc2(vv.x), VY  = bc2(vv.y), VZ  = bc2(vv.z);
        #pragma unroll
        for (int p = 0; p < 2; p++) {
            u64 t1 = fma2(QRX[p], KRX, KDW);
            t1 = fma2(QRY[p], KRY, t1);
            t1 = fma2(QRZ[p], KRZ, t1);
            u64 d2 = add2(Q2[p], KRW);
            d2 = fma2(QDX[p], KDX, d2);
            d2 = fma2(QDY[p], KDY, d2);
            d2 = fma2(QDZ[p], KDZ, d2);
            float d2a, d2b;
            up2(d2a, d2b, d2);
            float da, db, pa, pb;
            float ada = fabsf(d2a), adb = fabsf(d2b);
            asm("sqrt.approx.f32 %0, %1;" : "=f"(da) : "f"(ada));
            asm("sqrt.approx.f32 %0, %1;" : "=f"(db) : "f"(adb));
            u64 DD = pk2(da, db);
            u64 ARG = fma2(NB, DD, t1);
            float arga, argb;
            up2(arga, argb, ARG);
            asm("ex2.approx.f32 %0, %1;" : "=f"(pa) : "f"(arga));
            asm("ex2.approx.f32 %0, %1;" : "=f"(pb) : "f"(argb));
            u64 P = pk2(pa, pb);
            S [p] = add2(S[p], P);
            A0[p] = fma2(P, VX, A0[p]);
            A1[p] = fma2(P, VY, A1[p]);
            A2[p] = fma2(P, VZ, A2[p]);
        }
    }

    // cross-lane sum reduce
    int b = bh >> 4, h = bh & 15;
    #pragma unroll
    for (int p = 0; p < 2; p++) {
        float s0, s1, x0, x1, y0, y1, z0, z1;
        up2(s0, s1, S[p]); up2(x0, x1, A0[p]); up2(y0, y1, A1[p]); up2(z0, z1, A2[p]);
        #pragma unroll
        for (int o = 16; o; o >>= 1) {
            s0 += __shfl_xor_sync(0xFFFFFFFFu, s0, o);
            x0 += __shfl_xor_sync(0xFFFFFFFFu, x0, o);
            y0 += __shfl_xor_sync(0xFFFFFFFFu, y0, o);
            z0 += __shfl_xor_sync(0xFFFFFFFFu, z0, o);
            s1 += __shfl_xor_sync(0xFFFFFFFFu, s1, o);
            x1 += __shfl_xor_sync(0xFFFFFFFFu, x1, o);
            y1 += __shfl_xor_sync(0xFFFFFFFFu, y1, o);
            z1 += __shfl_xor_sync(0xFFFFFFFFu, z1, o);
        }
        if (lane == 0) {
            float inv0, inv1;
            asm("rcp.approx.f32 %0, %1;" : "=f"(inv0) : "f"(s0));
            asm("rcp.approx.f32 %0, %1;" : "=f"(inv1) : "f"(s1));
            int row0 = rbase + 2*p;
            float* op0 = g_O + ((size_t)(b * L + row0) * H + h) * 3;
            float* op1 = g_O + ((size_t)(b * L + row0 + 1) * H + h) * 3;
            op0[0] = x0 * inv0; op0[1] = y0 * inv0; op0[2] = z0 * inv0;
            op1[0] = x1 * inv1; op1[1] = y1 * inv1; op1[2] = z1 * inv1;
        }
    }
}

// ============================================================
// K4: rotate back (R^T) + output GEMM (48 -> 1024) + bias, f32x2
// 16 tokens per block (halves Wout re-reads), 256 threads.
// ============================================================
__global__ void __launch_bounds__(256) out_kernel(const float* __restrict__ rot,
                                                  const float* __restrict__ Wout,
                                                  const float* __restrict__ bout,
                                                  float* __restrict__ out)
{
    __shared__ float so[48][16];   // [k][token]
    int t0  = blockIdx.x * 16;
    int tid = threadIdx.x;

    {
        int tt = tid >> 4, h = tid & 15;   // 16 tokens x 16 heads = 256 threads
        int t = t0 + tt;
        const float* op = g_O + ((size_t)t * H + h) * 3;
        float R0 = rot[t*9+0], R1 = rot[t*9+1], R2 = rot[t*9+2];
        float R3 = rot[t*9+3], R4 = rot[t*9+4], R5 = rot[t*9+5];
        float R6 = rot[t*9+6], R7 = rot[t*9+7], R8 = rot[t*9+8];
        float o0 = op[0], o1 = op[1], o2 = op[2];
        so[h*3+0][tt] = R0*o0 + R3*o1 + R6*o2;
        so[h*3+1][tt] = R1*o0 + R4*o1 + R7*o2;
        so[h*3+2][tt] = R2*o0 + R5*o1 + R8*o2;
    }
    __syncthreads();

    int e0 = tid;   // cols e0, e0+256, e0+512, e0+768
    u64 acc[8][4];  // [tokenpair][colgroup]
    #pragma unroll
    for (int c = 0; c < 4; c++) {
        float bb = bout[e0 + 256*c];
        u64 bb2 = bc2(bb);
        #pragma unroll
        for (int tp = 0; tp < 8; tp++) acc[tp][c] = bb2;
    }

    #pragma unroll 4
    for (int k = 0; k < 48; k++) {
        u64 w2[4];
        #pragma unroll
        for (int c = 0; c < 4; c++) w2[c] = bc2(Wout[(size_t)k*E + e0 + 256*c]);
        const u64* sop = (const u64*)&so[k][0];
        #pragma unroll
        for (int tp = 0; tp < 8; tp++) {
            u64 sv = sop[tp];
            acc[tp][0] = fma2(sv, w2[0], acc[tp][0]);
            acc[tp][1] = fma2(sv, w2[1], acc[tp][1]);
            acc[tp][2] = fma2(sv, w2[2], acc[tp][2]);
            acc[tp][3] = fma2(sv, w2[3], acc[tp][3]);
        }
    }
    #pragma unroll
    for (int tp = 0; tp < 8; tp++) {
        float* orow0 = out + (size_t)(t0 + 2*tp) * E;
        float* orow1 = out + (size_t)(t0 + 2*tp + 1) * E;
        #pragma unroll
        for (int c = 0; c < 4; c++) {
            float lo, hi;
            up2(lo, hi, acc[tp][c]);
            orow0[e0 + 256*c] = lo;
            orow1[e0 + 256*c] = hi;
        }
    }
}

// ============================================================
extern "C" void kernel_launch(void* const* d_in, const int* in_sizes, int n_in,
                              void* d_out, int out_size)
{
    const float*         x       = (const float*)d_in[0];
    const float*         rot     = (const float*)d_in[1];
    const float*         trans   = (const float*)d_in[2];
    const unsigned char* mask    = (const unsigned char*)d_in[3];
    const float*         Wqkv    = (const float*)d_in[4];
    const float*         Wout    = (const float*)d_in[5];
    const float*         bout    = (const float*)d_in[6];
    const float*         gamma   = (const float*)d_in[7];
    const float*         beta    = (const float*)d_in[8];
    const float*         r_scale = (const float*)d_in[9];
    const float*         d_scale = (const float*)d_in[10];
    float* out = (float*)d_out;

    ln_kernel<<<NT, 256>>>(x, gamma, beta);
    qkv_gemm<<<dim3(NT/64, 5, KSPLIT), 128>>>(Wqkv);
    pack_kernel<<<(NT*H + 255)/256, 256>>>(rot, trans, mask, r_scale, d_scale);
    attn_kernel<<<dim3(B*H, L/32), 256>>>();
    out_kernel<<<NT/16, 256>>>(rot, Wout, bout, out);
}

// round 9
// speedup vs baseline: 1.0918x; 1.0207x over previous
#include <cuda_runtime.h>
#include <cuda_bf16.h>
#include <math_constants.h>

// Problem constants
#define B 2
#define L 1024
#define E 1024
#define H 16
#define NT (B*L)          // 2048 tokens
#define LOG2E 1.4426950408889634f
#define KSPLIT 8

typedef unsigned long long u64;

// -------- scratch (static __device__, no allocations) --------
__device__ float4 g_xn4[NT * (E/4)];             // layernormed x, 8MB
__device__ float  g_projp[KSPLIT][NT * 240];     // QKV projection partials
__device__ float4 g_Q[B*H*L * 2];                // per (b,h,i): (alpha'*Qr, q2), (qd, -beta')
__device__ float4 g_K[B*H*L * 3];                // per (b,h,j): (Kr, k2), (-2kd, maskpen'), (V, 0)
__device__ float  g_O[NT * H * 3];               // attention output (B,L,H,3)

// ---------------- f32x2 helpers ----------------
__device__ __forceinline__ u64 pk2(float lo, float hi)
{ u64 r; asm("mov.b64 %0, {%1,%2};" : "=l"(r) : "f"(lo), "f"(hi)); return r; }
__device__ __forceinline__ u64 bc2(float v) { return pk2(v, v); }
__device__ __forceinline__ void up2(float &lo, float &hi, u64 v)
{ asm("mov.b64 {%0,%1}, %2;" : "=f"(lo), "=f"(hi) : "l"(v)); }
__device__ __forceinline__ u64 fma2(u64 a, u64 b, u64 c)
{ u64 d; asm("fma.rn.f32x2 %0, %1, %2, %3;" : "=l"(d) : "l"(a), "l"(b), "l"(c)); return d; }
__device__ __forceinline__ u64 add2(u64 a, u64 b)
{ u64 d; asm("add.rn.f32x2 %0, %1, %2;" : "=l"(d) : "l"(a), "l"(b)); return d; }

// ============================================================
// K1: LayerNorm  (one block per token, 256 threads, float4)
// ============================================================
__global__ void __launch_bounds__(256) ln_kernel(const float* __restrict__ x,
                                                 const float* __restrict__ gamma,
                                                 const float* __restrict__ beta)
{
    int t   = blockIdx.x;
    int tid = threadIdx.x;
    const float4* xr = (const float4*)(x + (size_t)t * E);
    float4 v = xr[tid];
    float s  = v.x + v.y + v.z + v.w;
    float ss = v.x*v.x + v.y*v.y + v.z*v.z + v.w*v.w;
    #pragma unroll
    for (int o = 16; o; o >>= 1) {
        s  += __shfl_xor_sync(0xFFFFFFFFu, s,  o);
        ss += __shfl_xor_sync(0xFFFFFFFFu, ss, o);
    }
    __shared__ float sm[8], sm2[8];
    __shared__ float mu_s, rstd_s;
    if ((tid & 31) == 0) { sm[tid >> 5] = s; sm2[tid >> 5] = ss; }
    __syncthreads();
    if (tid == 0) {
        float S = 0.f, SS = 0.f;
        #pragma unroll
        for (int i = 0; i < 8; i++) { S += sm[i]; SS += sm2[i]; }
        float mu  = S * (1.0f / E);
        float var = SS * (1.0f / E) - mu * mu;
        mu_s   = mu;
        rstd_s = rsqrtf(var + 1e-5f);
    }
    __syncthreads();
    float mu = mu_s, r = rstd_s;
    float4 g  = ((const float4*)gamma)[tid];
    float4 be = ((const float4*)beta)[tid];
    float4 o;
    o.x = (v.x - mu) * r * g.x + be.x;
    o.y = (v.y - mu) * r * g.y + be.y;
    o.z = (v.z - mu) * r * g.z + be.z;
    o.w = (v.w - mu) * r * g.w + be.w;
    g_xn4[t * (E/4) + tid] = o;
}

// ============================================================
// K2: QKV GEMM, f32x2, CONFLICT-FREE staging.
// C[2048x240] = xn[2048x1024] @ Wqkv[1024x240]
// BM=64 BN=48, K-split 8 (z), 128 threads, micro 8 rows x 3 cols.
// A: XOR-swizzled [k][group] layout, stores conflict-free (proof in notes).
// B: duplicated col-pairs stored as STS.64, stride 98 (2-way max).
// ============================================================
__global__ void __launch_bounds__(128) qkv_gemm(const float* __restrict__ W)
{
    __shared__ float As[16 * 64];      // [k][swizzled group*4 + r3], 4KB
    __shared__ float Bs[16 * 98];      // [k][2*col] duplicated, stride 98, 6.3KB

    const float* xn = (const float*)g_xn4;
    int bm = blockIdx.x * 64;
    int bn = blockIdx.y * 48;
    int kh = blockIdx.z;                 // K eighth: 0..7
    int t  = threadIdx.x;
    int ty2 = (t >> 4) * 2;              // group base for this thread's 8 rows
    int tx = t & 15;                     // 0..15 -> cols tx*3

    u64 acc[4][3];
    #pragma unroll
    for (int i = 0; i < 4; i++)
        #pragma unroll
        for (int c = 0; c < 3; c++) acc[i][c] = 0ull;

    // A staging map
    int arow0 = t >> 2;                  // 0..31 (and +32)
    int akc   = (t & 3) * 4;             // k sub-block 0,4,8,12
    int aq2   = (t & 3) << 1;            // swizzle term = 2*(kidx>>2)

    // B staging map
    int bk  = t >> 3;                    // 0..15
    int bcf = (t & 7) * 6;               // source col offset 0,6,...,42

    const int KQ = 1024 / KSPLIT;        // 128
    for (int k0 = kh * KQ; k0 < kh * KQ + KQ; k0 += 16) {
        // stage A (conflict-free swizzled stores)
        #pragma unroll
        for (int i = 0; i < 2; i++) {
            int row = arow0 + 32 * i;
            float4 av = *(const float4*)(xn + (size_t)(bm + row) * E + k0 + akc);
            int gofs = (((row >> 2) ^ aq2) << 2) + (row & 3);
            As[(akc + 0) * 64 + gofs] = av.x;
            As[(akc + 1) * 64 + gofs] = av.y;
            As[(akc + 2) * 64 + gofs] = av.z;
            As[(akc + 3) * 64 + gofs] = av.w;
        }
        // stage B duplicated via STS.64
        {
            const float* wp = W + (size_t)(k0 + bk) * 240 + bn + bcf;
            float2 b0 = *(const float2*)(wp + 0);
            float2 b1 = *(const float2*)(wp + 2);
            float2 b2 = *(const float2*)(wp + 4);
            u64* bs = (u64*)&Bs[bk * 98 + bcf * 2];
            bs[0] = bc2(b0.x); bs[1] = bc2(b0.y);
            bs[2] = bc2(b1.x); bs[3] = bc2(b1.y);
            bs[4] = bc2(b2.x); bs[5] = bc2(b2.y);
        }
        __syncthreads();
        #pragma unroll
        for (int kk = 0; kk < 16; kk++) {
            const int q2 = (kk >> 2) << 1;
            const float* arow = &As[kk * 64 + ((ty2 ^ q2) << 2)];
            ulonglong2 a01 = *(const ulonglong2*)(arow);
            ulonglong2 a23 = *(const ulonglong2*)(arow + 4);
            const float* brow = &Bs[kk * 98 + tx * 6];
            u64 b0 = *(const u64*)(brow + 0);
            u64 b1 = *(const u64*)(brow + 2);
            u64 b2 = *(const u64*)(brow + 4);
            acc[0][0]=fma2(a01.x,b0,acc[0][0]); acc[0][1]=fma2(a01.x,b1,acc[0][1]); acc[0][2]=fma2(a01.x,b2,acc[0][2]);
            acc[1][0]=fma2(a01.y,b0,acc[1][0]); acc[1][1]=fma2(a01.y,b1,acc[1][1]); acc[1][2]=fma2(a01.y,b2,acc[1][2]);
            acc[2][0]=fma2(a23.x,b0,acc[2][0]); acc[2][1]=fma2(a23.x,b1,acc[2][1]); acc[2][2]=fma2(a23.x,b2,acc[2][2]);
            acc[3][0]=fma2(a23.y,b0,acc[3][0]); acc[3][1]=fma2(a23.y,b1,acc[3][1]); acc[3][2]=fma2(a23.y,b2,acc[3][2]);
        }
        __syncthreads();
    }

    float* out = g_projp[kh];
    int ty = t >> 4;
    #pragma unroll
    for (int i = 0; i < 4; i++) {
        int row = bm + ty * 8 + 2 * i;
        #pragma unroll
        for (int c = 0; c < 3; c++) {
            float lo, hi;
            up2(lo, hi, acc[i][c]);
            int col = bn + tx * 3 + c;
            out[(size_t)row * 240 + col]       = lo;
            out[(size_t)(row + 1) * 240 + col] = hi;
        }
    }
}

// ============================================================
// K2b: rotate + translate + pack per (token, head)
// ============================================================
__device__ __forceinline__ float softplus_f(float x)
{
    return (x > 20.f) ? x : log1pf(__expf(x));
}

__global__ void __launch_bounds__(256) pack_kernel(const float* __restrict__ rot,
                                                   const float* __restrict__ trans,
                                                   const unsigned char* __restrict__ mask,
                                                   const float* __restrict__ r_scale,
                                                   const float* __restrict__ d_scale)
{
    int gid = blockIdx.x * blockDim.x + threadIdx.x;
    if (gid >= NT * H) return;
    int t = gid >> 4;
    int h = gid & 15;

    float R[9];
    #pragma unroll
    for (int i = 0; i < 9; i++) R[i] = rot[t*9 + i];
    float T0 = trans[t*3+0], T1 = trans[t*3+1], T2 = trans[t*3+2];

    float y[5][3];
    #pragma unroll
    for (int f = 0; f < 5; f++) {
        int o = f*48 + h*3;
        float v0 = 0.f, v1 = 0.f, v2 = 0.f;
        #pragma unroll
        for (int q = 0; q < KSPLIT; q++) {
            const float* P = g_projp[q] + (size_t)t * 240;
            v0 += P[o+0]; v1 += P[o+1]; v2 += P[o+2];
        }
        y[f][0] = R[0]*v0 + R[1]*v1 + R[2]*v2;
        y[f][1] = R[3]*v0 + R[4]*v1 + R[5]*v2;
        y[f][2] = R[6]*v0 + R[7]*v1 + R[8]*v2;
    }
    const float scale = 0.5773502691896258f;      // 3^-0.5
    float alpha = softplus_f(r_scale[h]) * scale * LOG2E;
    float nbeta = -softplus_f(d_scale[h]) * scale * LOG2E;

    float qd0 = y[2][0] + T0, qd1 = y[2][1] + T1, qd2 = y[2][2] + T2;
    float q2  = qd0*qd0 + qd1*qd1 + qd2*qd2;
    float kd0 = y[3][0] + T0, kd1 = y[3][1] + T1, kd2 = y[3][2] + T2;
    float k2  = kd0*kd0 + kd1*kd1 + kd2*kd2;

    int b = t >> 10, l = t & 1023;
    int base = (b*H + h) * L + l;

    g_Q[base*2 + 0] = make_float4(alpha*y[0][0], alpha*y[0][1], alpha*y[0][2], q2);
    g_Q[base*2 + 1] = make_float4(qd0, qd1, qd2, nbeta);

    float mpen = mask[t] ? -2.0e9f : 0.f;   // in log2 units; EX2 -> 0
    g_K[base*3 + 0] = make_float4(y[1][0], y[1][1], y[1][2], k2);
    g_K[base*3 + 1] = make_float4(-2.f*kd0, -2.f*kd1, -2.f*kd2, mpen);
    g_K[base*3 + 2] = make_float4(y[4][0], y[4][1], y[4][2], 0.f);
}

// ============================================================
// K3: flash attention, geometric logits, no online max, f32x2 packed
// over row-pairs. Block: 8 warps x 4 rows = 32 i-rows; lanes split j.
// grid (B*H, L/32).  3 blocks/SM.   (proven version, unchanged)
// ============================================================
__global__ void __launch_bounds__(256, 3) attn_kernel()
{
    __shared__ float4 sk[L * 3];   // 49152 bytes

    int bh    = blockIdx.x;        // b*H + h
    int itile = blockIdx.y;        // 0..31

    const float4* Ksrc = g_K + (size_t)bh * L * 3;
    #pragma unroll
    for (int i = 0; i < 12; i++) sk[threadIdx.x + 256 * i] = Ksrc[threadIdx.x + 256 * i];
    __syncthreads();

    int warp = threadIdx.x >> 5, lane = threadIdx.x & 31;
    int rbase = itile * 32 + warp * 4;

    const float4* Qsrc = g_Q + (size_t)(bh * L + rbase) * 2;
    u64 QRX[2], QRY[2], QRZ[2], Q2[2], QDX[2], QDY[2], QDZ[2];
    u64 S[2], A0[2], A1[2], A2[2];
    u64 NB;
    #pragma unroll
    for (int p = 0; p < 2; p++) {
        float4 alo = Qsrc[(2*p)*2],     blo = Qsrc[(2*p)*2 + 1];
        float4 ahi = Qsrc[(2*p+1)*2],   bhi = Qsrc[(2*p+1)*2 + 1];
        QRX[p] = pk2(alo.x, ahi.x); QRY[p] = pk2(alo.y, ahi.y);
        QRZ[p] = pk2(alo.z, ahi.z); Q2 [p] = pk2(alo.w, ahi.w);
        QDX[p] = pk2(blo.x, bhi.x); QDY[p] = pk2(blo.y, bhi.y);
        QDZ[p] = pk2(blo.z, bhi.z);
        if (p == 0) NB = bc2(blo.w);
        S[p] = 0ull; A0[p] = 0ull; A1[p] = 0ull; A2[p] = 0ull;
    }

    #pragma unroll 4
    for (int jj = 0; jj < 32; jj++) {
        int j = jj * 32 + lane;
        float4 kr = sk[j*3 + 0];
        float4 kd = sk[j*3 + 1];
        float4 vv = sk[j*3 + 2];
        u64 KRX = bc2(kr.x), KRY = bc2(kr.y), KRZ = bc2(kr.z), KRW = bc2(kr.w);
        u64 KDX = bc2(kd.x), KDY = bc2(kd.y), KDZ = bc2(kd.z), KDW = bc2(kd.w);
        u64 VX  = bc2(vv.x), VY  = bc2(vv.y), VZ  = bc2(vv.z);
        #pragma unroll
        for (int p = 0; p < 2; p++) {
            u64 t1 = fma2(QRX[p], KRX, KDW);
            t1 = fma2(QRY[p], KRY, t1);
            t1 = fma2(QRZ[p], KRZ, t1);
            u64 d2 = add2(Q2[p], KRW);
            d2 = fma2(QDX[p], KDX, d2);
            d2 = fma2(QDY[p], KDY, d2);
            d2 = fma2(QDZ[p], KDZ, d2);
            float d2a, d2b;
            up2(d2a, d2b, d2);
            float da, db, pa, pb;
            float ada = fabsf(d2a), adb = fabsf(d2b);
            asm("sqrt.approx.f32 %0, %1;" : "=f"(da) : "f"(ada));
            asm("sqrt.approx.f32 %0, %1;" : "=f"(db) : "f"(adb));
            u64 DD = pk2(da, db);
            u64 ARG = fma2(NB, DD, t1);
            float arga, argb;
            up2(arga, argb, ARG);
            asm("ex2.approx.f32 %0, %1;" : "=f"(pa) : "f"(arga));
            asm("ex2.approx.f32 %0, %1;" : "=f"(pb) : "f"(argb));
            u64 P = pk2(pa, pb);
            S [p] = add2(S[p], P);
            A0[p] = fma2(P, VX, A0[p]);
            A1[p] = fma2(P, VY, A1[p]);
            A2[p] = fma2(P, VZ, A2[p]);
        }
    }

    // cross-lane sum reduce
    int b = bh >> 4, h = bh & 15;
    #pragma unroll
    for (int p = 0; p < 2; p++) {
        float s0, s1, x0, x1, y0, y1, z0, z1;
        up2(s0, s1, S[p]); up2(x0, x1, A0[p]); up2(y0, y1, A1[p]); up2(z0, z1, A2[p]);
        #pragma unroll
        for (int o = 16; o; o >>= 1) {
            s0 += __shfl_xor_sync(0xFFFFFFFFu, s0, o);
            x0 += __shfl_xor_sync(0xFFFFFFFFu, x0, o);
            y0 += __shfl_xor_sync(0xFFFFFFFFu, y0, o);
            z0 += __shfl_xor_sync(0xFFFFFFFFu, z0, o);
            s1 += __shfl_xor_sync(0xFFFFFFFFu, s1, o);
            x1 += __shfl_xor_sync(0xFFFFFFFFu, x1, o);
            y1 += __shfl_xor_sync(0xFFFFFFFFu, y1, o);
            z1 += __shfl_xor_sync(0xFFFFFFFFu, z1, o);
        }
        if (lane == 0) {
            float inv0, inv1;
            asm("rcp.approx.f32 %0, %1;" : "=f"(inv0) : "f"(s0));
            asm("rcp.approx.f32 %0, %1;" : "=f"(inv1) : "f"(s1));
            int row0 = rbase + 2*p;
            float* op0 = g_O + ((size_t)(b * L + row0) * H + h) * 3;
            float* op1 = g_O + ((size_t)(b * L + row0 + 1) * H + h) * 3;
            op0[0] = x0 * inv0; op0[1] = y0 * inv0; op0[2] = z0 * inv0;
            op1[0] = x1 * inv1; op1[1] = y1 * inv1; op1[2] = z1 * inv1;
        }
    }
}

// ============================================================
// K4: rotate back (R^T) + output GEMM (48 -> 1024) + bias, f32x2
// 16 tokens per block, 256 threads.
// ============================================================
__global__ void __launch_bounds__(256) out_kernel(const float* __restrict__ rot,
                                                  const float* __restrict__ Wout,
                                                  const float* __restrict__ bout,
                                                  float* __restrict__ out)
{
    __shared__ float so[48][16];   // [k][token]
    int t0  = blockIdx.x * 16;
    int tid = threadIdx.x;

    {
        int tt = tid >> 4, h = tid & 15;   // 16 tokens x 16 heads = 256 threads
        int t = t0 + tt;
        const float* op = g_O + ((size_t)t * H + h) * 3;
        float R0 = rot[t*9+0], R1 = rot[t*9+1], R2 = rot[t*9+2];
        float R3 = rot[t*9+3], R4 = rot[t*9+4], R5 = rot[t*9+5];
        float R6 = rot[t*9+6], R7 = rot[t*9+7], R8 = rot[t*9+8];
        float o0 = op[0], o1 = op[1], o2 = op[2];
        so[h*3+0][tt] = R0*o0 + R3*o1 + R6*o2;
        so[h*3+1][tt] = R1*o0 + R4*o1 + R7*o2;
        so[h*3+2][tt] = R2*o0 + R5*o1 + R8*o2;
    }
    __syncthreads();

    int e0 = tid;   // cols e0, e0+256, e0+512, e0+768
    u64 acc[8][4];  // [tokenpair][colgroup]
    #pragma unroll
    for (int c = 0; c < 4; c++) {
        float bb = bout[e0 + 256*c];
        u64 bb2 = bc2(bb);
        #pragma unroll
        for (int tp = 0; tp < 8; tp++) acc[tp][c] = bb2;
    }

    #pragma unroll 4
    for (int k = 0; k < 48; k++) {
        u64 w2[4];
        #pragma unroll
        for (int c = 0; c < 4; c++) w2[c] = bc2(Wout[(size_t)k*E + e0 + 256*c]);
        const u64* sop = (const u64*)&so[k][0];
        #pragma unroll
        for (int tp = 0; tp < 8; tp++) {
            u64 sv = sop[tp];
            acc[tp][0] = fma2(sv, w2[0], acc[tp][0]);
            acc[tp][1] = fma2(sv, w2[1], acc[tp][1]);
            acc[tp][2] = fma2(sv, w2[2], acc[tp][2]);
            acc[tp][3] = fma2(sv, w2[3], acc[tp][3]);
        }
    }
    #pragma unroll
    for (int tp = 0; tp < 8; tp++) {
        float* orow0 = out + (size_t)(t0 + 2*tp) * E;
        float* orow1 = out + (size_t)(t0 + 2*tp + 1) * E;
        #pragma unroll
        for (int c = 0; c < 4; c++) {
            float lo, hi;
            up2(lo, hi, acc[tp][c]);
            orow0[e0 + 256*c] = lo;
            orow1[e0 + 256*c] = hi;
        }
    }
}

// ============================================================
extern "C" void kernel_launch(void* const* d_in, const int* in_sizes, int n_in,
                              void* d_out, int out_size)
{
    const float*         x       = (const float*)d_in[0];
    const float*         rot     = (const float*)d_in[1];
    const float*         trans   = (const float*)d_in[2];
    const unsigned char* mask    = (const unsigned char*)d_in[3];
    const float*         Wqkv    = (const float*)d_in[4];
    const float*         Wout    = (const float*)d_in[5];
    const float*         bout    = (const float*)d_in[6];
    const float*         gamma   = (const float*)d_in[7];
    const float*         beta    = (const float*)d_in[8];
    const float*         r_scale = (const float*)d_in[9];
    const float*         d_scale = (const float*)d_in[10];
    float* out = (float*)d_out;

    ln_kernel<<<NT, 256>>>(x, gamma, beta);
    qkv_gemm<<<dim3(NT/64, 5, KSPLIT), 128>>>(Wqkv);
    pack_kernel<<<(NT*H + 255)/256, 256>>>(rot, trans, mask, r_scale, d_scale);
    attn_kernel<<<dim3(B*H, L/32), 256>>>();
    out_kernel<<<NT/16, 256>>>(rot, Wout, bout, out);
}

// round 10
// speedup vs baseline: 1.0951x; 1.0030x over previous
#include <cuda_runtime.h>
#include <cuda_bf16.h>
#include <math_constants.h>

// Problem constants
#define B 2
#define L 1024
#define E 1024
#define H 16
#define NT (B*L)          // 2048 tokens
#define LOG2E 1.4426950408889634f
#define KSPLIT 8

typedef unsigned long long u64;

// -------- scratch (static __device__, no allocations) --------
__device__ float2 g_stats[NT];                   // per-token (mu, rstd)
__device__ float  g_projp[KSPLIT][NT * 240];     // QKV projection partials
__device__ float4 g_Q[B*H*L * 2];                // per (b,h,i): (alpha'*Qr, q2), (qd, -beta')
__device__ float4 g_K[B*H*L * 3];                // per (b,h,j): (Kr, k2), (-2kd, maskpen'), (V, 0)
__device__ float  g_O[NT * H * 3];               // attention output (B,L,H,3)

// ---------------- f32x2 helpers ----------------
__device__ __forceinline__ u64 pk2(float lo, float hi)
{ u64 r; asm("mov.b64 %0, {%1,%2};" : "=l"(r) : "f"(lo), "f"(hi)); return r; }
__device__ __forceinline__ u64 bc2(float v) { return pk2(v, v); }
__device__ __forceinline__ void up2(float &lo, float &hi, u64 v)
{ asm("mov.b64 {%0,%1}, %2;" : "=f"(lo), "=f"(hi) : "l"(v)); }
__device__ __forceinline__ u64 fma2(u64 a, u64 b, u64 c)
{ u64 d; asm("fma.rn.f32x2 %0, %1, %2, %3;" : "=l"(d) : "l"(a), "l"(b), "l"(c)); return d; }
__device__ __forceinline__ u64 add2(u64 a, u64 b)
{ u64 d; asm("add.rn.f32x2 %0, %1, %2;" : "=l"(d) : "l"(a), "l"(b)); return d; }

// ============================================================
// K1: LayerNorm STATS ONLY (mu, rstd per token) — normalization
// itself is fused into qkv_gemm's A-staging.
// ============================================================
__global__ void __launch_bounds__(256) ln_stats(const float* __restrict__ x)
{
    int t   = blockIdx.x;
    int tid = threadIdx.x;
    const float4* xr = (const float4*)(x + (size_t)t * E);
    float4 v = xr[tid];
    float s  = v.x + v.y + v.z + v.w;
    float ss = v.x*v.x + v.y*v.y + v.z*v.z + v.w*v.w;
    #pragma unroll
    for (int o = 16; o; o >>= 1) {
        s  += __shfl_xor_sync(0xFFFFFFFFu, s,  o);
        ss += __shfl_xor_sync(0xFFFFFFFFu, ss, o);
    }
    __shared__ float sm[8], sm2[8];
    if ((tid & 31) == 0) { sm[tid >> 5] = s; sm2[tid >> 5] = ss; }
    __syncthreads();
    if (tid == 0) {
        float S = 0.f, SS = 0.f;
        #pragma unroll
        for (int i = 0; i < 8; i++) { S += sm[i]; SS += sm2[i]; }
        float mu  = S * (1.0f / E);
        float var = SS * (1.0f / E) - mu * mu;
        g_stats[t] = make_float2(mu, rsqrtf(var + 1e-5f));
    }
}

// ============================================================
// K2: QKV GEMM, f32x2, conflict-free staging, LN fused on stage.
// C[2048x240] = LN(x)[2048x1024] @ Wqkv[1024x240]
// BM=64 BN=48, K-split 8 (z), 128 threads, micro 8 rows x 3 cols.
// ============================================================
__global__ void __launch_bounds__(128) qkv_gemm(const float* __restrict__ x,
                                                const float* __restrict__ gamma,
                                                const float* __restrict__ beta,
                                                const float* __restrict__ W)
{
    __shared__ float As[16 * 64];      // [k][swizzled group*4 + r3], 4KB
    __shared__ float Bs[16 * 98];      // [k][2*col] duplicated, stride 98, 6.3KB

    int bm = blockIdx.x * 64;
    int bn = blockIdx.y * 48;
    int kh = blockIdx.z;                 // K eighth: 0..7
    int t  = threadIdx.x;
    int ty2 = (t >> 4) * 2;              // group base for this thread's 8 rows
    int tx = t & 15;                     // 0..15 -> cols tx*3

    u64 acc[4][3];
    #pragma unroll
    for (int i = 0; i < 4; i++)
        #pragma unroll
        for (int c = 0; c < 3; c++) acc[i][c] = 0ull;

    // A staging map
    int arow0 = t >> 2;                  // 0..31 (and +32)
    int akc   = (t & 3) * 4;             // k sub-block 0,4,8,12
    int aq2   = (t & 3) << 1;            // swizzle term = 2*(kidx>>2)

    // B staging map
    int bk  = t >> 3;                    // 0..15
    int bcf = (t & 7) * 6;               // source col offset 0,6,...,42

    // LN stats for this thread's two staged rows (loop-invariant)
    float2 st[2];
    st[0] = g_stats[bm + arow0];
    st[1] = g_stats[bm + arow0 + 32];

    const int KQ = 1024 / KSPLIT;        // 128
    for (int k0 = kh * KQ; k0 < kh * KQ + KQ; k0 += 16) {
        // gamma/beta for this k sub-block (shared by both staged rows)
        float4 ga = *(const float4*)(gamma + k0 + akc);
        float4 bt = *(const float4*)(beta  + k0 + akc);
        // stage A (conflict-free swizzled stores, LN applied inline)
        #pragma unroll
        for (int i = 0; i < 2; i++) {
            int row = arow0 + 32 * i;
            float4 av = *(const float4*)(x + (size_t)(bm + row) * E + k0 + akc);
            float mu = st[i].x, rs = st[i].y;
            int gofs = (((row >> 2) ^ aq2) << 2) + (row & 3);
            As[(akc + 0) * 64 + gofs] = fmaf((av.x - mu) * rs, ga.x, bt.x);
            As[(akc + 1) * 64 + gofs] = fmaf((av.y - mu) * rs, ga.y, bt.y);
            As[(akc + 2) * 64 + gofs] = fmaf((av.z - mu) * rs, ga.z, bt.z);
            As[(akc + 3) * 64 + gofs] = fmaf((av.w - mu) * rs, ga.w, bt.w);
        }
        // stage B duplicated via STS.64
        {
            const float* wp = W + (size_t)(k0 + bk) * 240 + bn + bcf;
            float2 b0 = *(const float2*)(wp + 0);
            float2 b1 = *(const float2*)(wp + 2);
            float2 b2 = *(const float2*)(wp + 4);
            u64* bs = (u64*)&Bs[bk * 98 + bcf * 2];
            bs[0] = bc2(b0.x); bs[1] = bc2(b0.y);
            bs[2] = bc2(b1.x); bs[3] = bc2(b1.y);
            bs[4] = bc2(b2.x); bs[5] = bc2(b2.y);
        }
        __syncthreads();
        #pragma unroll
        for (int kk = 0; kk < 16; kk++) {
            const int q2 = (kk >> 2) << 1;
            const float* arow = &As[kk * 64 + ((ty2 ^ q2) << 2)];
            ulonglong2 a01 = *(const ulonglong2*)(arow);
            ulonglong2 a23 = *(const ulonglong2*)(arow + 4);
            const float* brow = &Bs[kk * 98 + tx * 6];
            u64 b0 = *(const u64*)(brow + 0);
            u64 b1 = *(const u64*)(brow + 2);
            u64 b2 = *(const u64*)(brow + 4);
            acc[0][0]=fma2(a01.x,b0,acc[0][0]); acc[0][1]=fma2(a01.x,b1,acc[0][1]); acc[0][2]=fma2(a01.x,b2,acc[0][2]);
            acc[1][0]=fma2(a01.y,b0,acc[1][0]); acc[1][1]=fma2(a01.y,b1,acc[1][1]); acc[1][2]=fma2(a01.y,b2,acc[1][2]);
            acc[2][0]=fma2(a23.x,b0,acc[2][0]); acc[2][1]=fma2(a23.x,b1,acc[2][1]); acc[2][2]=fma2(a23.x,b2,acc[2][2]);
            acc[3][0]=fma2(a23.y,b0,acc[3][0]); acc[3][1]=fma2(a23.y,b1,acc[3][1]); acc[3][2]=fma2(a23.y,b2,acc[3][2]);
        }
        __syncthreads();
    }

    float* out = g_projp[kh];
    int ty = t >> 4;
    #pragma unroll
    for (int i = 0; i < 4; i++) {
        int row = bm + ty * 8 + 2 * i;
        #pragma unroll
        for (int c = 0; c < 3; c++) {
            float lo, hi;
            up2(lo, hi, acc[i][c]);
            int col = bn + tx * 3 + c;
            out[(size_t)row * 240 + col]       = lo;
            out[(size_t)(row + 1) * 240 + col] = hi;
        }
    }
}

// ============================================================
// K2b: rotate + translate + pack per (token, head)
// ============================================================
__device__ __forceinline__ float softplus_f(float x)
{
    return (x > 20.f) ? x : log1pf(__expf(x));
}

__global__ void __launch_bounds__(256) pack_kernel(const float* __restrict__ rot,
                                                   const float* __restrict__ trans,
                                                   const unsigned char* __restrict__ mask,
                                                   const float* __restrict__ r_scale,
                                                   const float* __restrict__ d_scale)
{
    int gid = blockIdx.x * blockDim.x + threadIdx.x;
    if (gid >= NT * H) return;
    int t = gid >> 4;
    int h = gid & 15;

    float R[9];
    #pragma unroll
    for (int i = 0; i < 9; i++) R[i] = rot[t*9 + i];
    float T0 = trans[t*3+0], T1 = trans[t*3+1], T2 = trans[t*3+2];

    float y[5][3];
    #pragma unroll
    for (int f = 0; f < 5; f++) {
        int o = f*48 + h*3;
        float v0 = 0.f, v1 = 0.f, v2 = 0.f;
        #pragma unroll
        for (int q = 0; q < KSPLIT; q++) {
            const float* P = g_projp[q] + (size_t)t * 240;
            v0 += P[o+0]; v1 += P[o+1]; v2 += P[o+2];
        }
        y[f][0] = R[0]*v0 + R[1]*v1 + R[2]*v2;
        y[f][1] = R[3]*v0 + R[4]*v1 + R[5]*v2;
        y[f][2] = R[6]*v0 + R[7]*v1 + R[8]*v2;
    }
    const float scale = 0.5773502691896258f;      // 3^-0.5
    float alpha = softplus_f(r_scale[h]) * scale * LOG2E;
    float nbeta = -softplus_f(d_scale[h]) * scale * LOG2E;

    float qd0 = y[2][0] + T0, qd1 = y[2][1] + T1, qd2 = y[2][2] + T2;
    float q2  = qd0*qd0 + qd1*qd1 + qd2*qd2;
    float kd0 = y[3][0] + T0, kd1 = y[3][1] + T1, kd2 = y[3][2] + T2;
    float k2  = kd0*kd0 + kd1*kd1 + kd2*kd2;

    int b = t >> 10, l = t & 1023;
    int base = (b*H + h) * L + l;

    g_Q[base*2 + 0] = make_float4(alpha*y[0][0], alpha*y[0][1], alpha*y[0][2], q2);
    g_Q[base*2 + 1] = make_float4(qd0, qd1, qd2, nbeta);

    float mpen = mask[t] ? -2.0e9f : 0.f;   // in log2 units; EX2 -> 0
    g_K[base*3 + 0] = make_float4(y[1][0], y[1][1], y[1][2], k2);
    g_K[base*3 + 1] = make_float4(-2.f*kd0, -2.f*kd1, -2.f*kd2, mpen);
    g_K[base*3 + 2] = make_float4(y[4][0], y[4][1], y[4][2], 0.f);
}

// ============================================================
// K3: flash attention, geometric logits, no online max, f32x2 packed
// over row-pairs. Block: 8 warps x 4 rows = 32 i-rows; lanes split j.
// grid (B*H, L/32).  Forced 4 blocks/SM (regs capped to 64).
// ============================================================
__global__ void __launch_bounds__(256, 4) attn_kernel()
{
    __shared__ float4 sk[L * 3];   // 49152 bytes

    int bh    = blockIdx.x;        // b*H + h
    int itile = blockIdx.y;        // 0..31

    const float4* Ksrc = g_K + (size_t)bh * L * 3;
    #pragma unroll
    for (int i = 0; i < 12; i++) sk[threadIdx.x + 256 * i] = Ksrc[threadIdx.x + 256 * i];
    __syncthreads();

    int warp = threadIdx.x >> 5, lane = threadIdx.x & 31;
    int rbase = itile * 32 + warp * 4;

    const float4* Qsrc = g_Q + (size_t)(bh * L + rbase) * 2;
    u64 QRX[2], QRY[2], QRZ[2], Q2[2], QDX[2], QDY[2], QDZ[2];
    u64 S[2], A0[2], A1[2], A2[2];
    u64 NB;
    #pragma unroll
    for (int p = 0; p < 2; p++) {
        float4 alo = Qsrc[(2*p)*2],     blo = Qsrc[(2*p)*2 + 1];
        float4 ahi = Qsrc[(2*p+1)*2],   bhi = Qsrc[(2*p+1)*2 + 1];
        QRX[p] = pk2(alo.x, ahi.x); QRY[p] = pk2(alo.y, ahi.y);
        QRZ[p] = pk2(alo.z, ahi.z); Q2 [p] = pk2(alo.w, ahi.w);
        QDX[p] = pk2(blo.x, bhi.x); QDY[p] = pk2(blo.y, bhi.y);
        QDZ[p] = pk2(blo.z, bhi.z);
        if (p == 0) NB = bc2(blo.w);
        S[p] = 0ull; A0[p] = 0ull; A1[p] = 0ull; A2[p] = 0ull;
    }

    #pragma unroll 4
    for (int jj = 0; jj < 32; jj++) {
        int j = jj * 32 + lane;
        float4 kr = sk[j*3 + 0];
        float4 kd = sk[j*3 + 1];
        float4 vv = sk[j*3 + 2];
        u64 KRX = bc2(kr.x), KRY = bc2(kr.y), KRZ = bc2(kr.z), KRW = bc2(kr.w);
        u64 KDX = bc2(kd.x), KDY = bc2(kd.y), KDZ = bc2(kd.z), KDW = bc2(kd.w);
        u64 VX  = bc2(vv.x), VY  = bc2(vv.y), VZ  = bc2(vv.z);
        #pragma unroll
        for (int p = 0; p < 2; p++) {
            u64 t1 = fma2(QRX[p], KRX, KDW);
            t1 = fma2(QRY[p], KRY, t1);
            t1 = fma2(QRZ[p], KRZ, t1);
            u64 d2 = add2(Q2[p], KRW);
            d2 = fma2(QDX[p], KDX, d2);
            d2 = fma2(QDY[p], KDY, d2);
            d2 = fma2(QDZ[p], KDZ, d2);
            float d2a, d2b;
            up2(d2a, d2b, d2);
            float da, db, pa, pb;
            float ada = fabsf(d2a), adb = fabsf(d2b);
            asm("sqrt.approx.f32 %0, %1;" : "=f"(da) : "f"(ada));
            asm("sqrt.approx.f32 %0, %1;" : "=f"(db) : "f"(adb));
            u64 DD = pk2(da, db);
            u64 ARG = fma2(NB, DD, t1);
            float arga, argb;
            up2(arga, argb, ARG);
            asm("ex2.approx.f32 %0, %1;" : "=f"(pa) : "f"(arga));
            asm("ex2.approx.f32 %0, %1;" : "=f"(pb) : "f"(argb));
            u64 P = pk2(pa, pb);
            S [p] = add2(S[p], P);
            A0[p] = fma2(P, VX, A0[p]);
            A1[p] = fma2(P, VY, A1[p]);
            A2[p] = fma2(P, VZ, A2[p]);
        }
    }

    // cross-lane sum reduce
    int b = bh >> 4, h = bh & 15;
    #pragma unroll
    for (int p = 0; p < 2; p++) {
        float s0, s1, x0, x1, y0, y1, z0, z1;
        up2(s0, s1, S[p]); up2(x0, x1, A0[p]); up2(y0, y1, A1[p]); up2(z0, z1, A2[p]);
        #pragma unroll
        for (int o = 16; o; o >>= 1) {
            s0 += __shfl_xor_sync(0xFFFFFFFFu, s0, o);
            x0 += __shfl_xor_sync(0xFFFFFFFFu, x0, o);
            y0 += __shfl_xor_sync(0xFFFFFFFFu, y0, o);
            z0 += __shfl_xor_sync(0xFFFFFFFFu, z0, o);
            s1 += __shfl_xor_sync(0xFFFFFFFFu, s1, o);
            x1 += __shfl_xor_sync(0xFFFFFFFFu, x1, o);
            y1 += __shfl_xor_sync(0xFFFFFFFFu, y1, o);
            z1 += __shfl_xor_sync(0xFFFFFFFFu, z1, o);
        }
        if (lane == 0) {
            float inv0, inv1;
            asm("rcp.approx.f32 %0, %1;" : "=f"(inv0) : "f"(s0));
            asm("rcp.approx.f32 %0, %1;" : "=f"(inv1) : "f"(s1));
            int row0 = rbase + 2*p;
            float* op0 = g_O + ((size_t)(b * L + row0) * H + h) * 3;
            float* op1 = g_O + ((size_t)(b * L + row0 + 1) * H + h) * 3;
            op0[0] = x0 * inv0; op0[1] = y0 * inv0; op0[2] = z0 * inv0;
            op1[0] = x1 * inv1; op1[1] = y1 * inv1; op1[2] = z1 * inv1;
        }
    }
}

// ============================================================
// K4: rotate back (R^T) + output GEMM (48 -> 1024) + bias, f32x2
// 16 tokens per block, 256 threads.
// ============================================================
__global__ void __launch_bounds__(256) out_kernel(const float* __restrict__ rot,
                                                  const float* __restrict__ Wout,
                                                  const float* __restrict__ bout,
                                                  float* __restrict__ out)
{
    __shared__ float so[48][16];   // [k][token]
    int t0  = blockIdx.x * 16;
    int tid = threadIdx.x;

    {
        int tt = tid >> 4, h = tid & 15;   // 16 tokens x 16 heads = 256 threads
        int t = t0 + tt;
        const float* op = g_O + ((size_t)t * H + h) * 3;
        float R0 = rot[t*9+0], R1 = rot[t*9+1], R2 = rot[t*9+2];
        float R3 = rot[t*9+3], R4 = rot[t*9+4], R5 = rot[t*9+5];
        float R6 = rot[t*9+6], R7 = rot[t*9+7], R8 = rot[t*9+8];
        float o0 = op[0], o1 = op[1], o2 = op[2];
        so[h*3+0][tt] = R0*o0 + R3*o1 + R6*o2;
        so[h*3+1][tt] = R1*o0 + R4*o1 + R7*o2;
        so[h*3+2][tt] = R2*o0 + R5*o1 + R8*o2;
    }
    __syncthreads();

    int e0 = tid;   // cols e0, e0+256, e0+512, e0+768
    u64 acc[8][4];  // [tokenpair][colgroup]
    #pragma unroll
    for (int c = 0; c < 4; c++) {
        float bb = bout[e0 + 256*c];
        u64 bb2 = bc2(bb);
        #pragma unroll
        for (int tp = 0; tp < 8; tp++) acc[tp][c] = bb2;
    }

    #pragma unroll 4
    for (int k = 0; k < 48; k++) {
        u64 w2[4];
        #pragma unroll
        for (int c = 0; c < 4; c++) w2[c] = bc2(Wout[(size_t)k*E + e0 + 256*c]);
        const u64* sop = (const u64*)&so[k][0];
        #pragma unroll
        for (int tp = 0; tp < 8; tp++) {
            u64 sv = sop[tp];
            acc[tp][0] = fma2(sv, w2[0], acc[tp][0]);
            acc[tp][1] = fma2(sv, w2[1], acc[tp][1]);
            acc[tp][2] = fma2(sv, w2[2], acc[tp][2]);
            acc[tp][3] = fma2(sv, w2[3], acc[tp][3]);
        }
    }
    #pragma unroll
    for (int tp = 0; tp < 8; tp++) {
        float* orow0 = out + (size_t)(t0 + 2*tp) * E;
        float* orow1 = out + (size_t)(t0 + 2*tp + 1) * E;
        #pragma unroll
        for (int c = 0; c < 4; c++) {
            float lo, hi;
            up2(lo, hi, acc[tp][c]);
            orow0[e0 + 256*c] = lo;
            orow1[e0 + 256*c] = hi;
        }
    }
}

// ============================================================
extern "C" void kernel_launch(void* const* d_in, const int* in_sizes, int n_in,
                              void* d_out, int out_size)
{
    const float*         x       = (const float*)d_in[0];
    const float*         rot     = (const float*)d_in[1];
    const float*         trans   = (const float*)d_in[2];
    const unsigned char* mask    = (const unsigned char*)d_in[3];
    const float*         Wqkv    = (const float*)d_in[4];
    const float*         Wout    = (const float*)d_in[5];
    const float*         bout    = (const float*)d_in[6];
    const float*         gamma   = (const float*)d_in[7];
    const float*         beta    = (const float*)d_in[8];
    const float*         r_scale = (const float*)d_in[9];
    const float*         d_scale = (const float*)d_in[10];
    float* out = (float*)d_out;

    ln_stats<<<NT, 256>>>(x);
    qkv_gemm<<<dim3(NT/64, 5, KSPLIT), 128>>>(x, gamma, beta, Wqkv);
    pack_kernel<<<(NT*H + 255)/256, 256>>>(rot, trans, mask, r_scale, d_scale);
    attn_kernel<<<dim3(B*H, L/32), 256>>>();
    out_kernel<<<NT/16, 256>>>(rot, Wout, bout, out);
}